// round 4
// baseline (speedup 1.0000x reference)
#include <cuda_runtime.h>

// ---------------- problem constants ----------------
#define NLAYERS 4
#define BATCH   8
#define SEQ     512
#define DMODEL  512
#define ED      1024      // EXPAND * DMODEL
#define DSTATE  16
#define DTRANK  32
#define DCONV   4
#define TOK     (BATCH*SEQ)   // 4096

// ---------------- scratch buffers (device globals; no allocation) ----------------
__device__ __align__(16) float g_xbuf [TOK*DMODEL];   // residual stream
__device__ __align__(16) float g_xn   [TOK*DMODEL];   // rmsnorm output
__device__ __align__(16) float g_xz   [TOK*2*ED];     // in_proj output (xb | z)
__device__ __align__(16) float g_xc   [TOK*ED];       // conv+silu output
__device__ __align__(16) float g_dbc  [TOK*64];       // x_proj output (dt|B|C)
__device__ __align__(16) float g_delta[TOK*ED];       // softplus(dt_proj)
__device__ __align__(16) float g_y    [TOK*ED];       // scan output (gated)

// ---------------- rmsnorm: one block per token ----------------
__global__ void rmsnorm_kernel(const float* __restrict__ w) {
    const int tkn = blockIdx.x;
    const float* xr = g_xbuf + (long)tkn * DMODEL;
    float* o = g_xn + (long)tkn * DMODEL;
    const int t = threadIdx.x;   // 128 threads, 4 elems each
    float v[4];
    float s = 0.f;
#pragma unroll
    for (int i = 0; i < 4; i++) { v[i] = xr[t + i*128]; s += v[i]*v[i]; }
#pragma unroll
    for (int off = 16; off; off >>= 1) s += __shfl_xor_sync(0xffffffffu, s, off);
    __shared__ float sh[4];
    if ((t & 31) == 0) sh[t >> 5] = s;
    __syncthreads();
    const float tot = sh[0] + sh[1] + sh[2] + sh[3];
    const float scale = rsqrtf(tot * (1.0f/DMODEL) + 1e-5f);
#pragma unroll
    for (int i = 0; i < 4; i++) o[t + i*128] = v[i] * scale * __ldg(&w[t + i*128]);
}

// ---------------- generic fp32 GEMM: C[M,N] = A[M,K] * B[N,K]^T ----------------
// EPI: 0 = store, 1 = softplus(acc + bias[n]), 2 = C += acc (residual)
// tiles: BM=128, BN=64, BK=16; 256 threads; 8x4 per-thread micro-tile
template<int EPI>
__global__ void __launch_bounds__(256) gemm_abt(
    const float* __restrict__ A, int lda,
    const float* __restrict__ B, int ldb,
    float* __restrict__ C, int ldc,
    int K, const float* __restrict__ bias)
{
    __shared__ float As[16][132];   // k-major, padded
    __shared__ float Bs[16][68];

    const int t  = threadIdx.x;
    const int tx = t & 15;          // n direction (x4)
    const int ty = t >> 4;          // m direction (x8)
    const int mb = blockIdx.y * 128;
    const int nb = blockIdx.x * 64;

    const int lrow = t >> 2;        // 0..63
    const int lk   = (t & 3) << 2;  // 0,4,8,12

    const float* Ap0 = A + (long)(mb + lrow)      * lda + lk;
    const float* Ap1 = A + (long)(mb + lrow + 64) * lda + lk;
    const float* Bp  = B + (long)(nb + lrow)      * ldb + lk;

    float c[8][4];
#pragma unroll
    for (int i = 0; i < 8; i++)
#pragma unroll
        for (int j = 0; j < 4; j++) c[i][j] = 0.f;

#pragma unroll 2
    for (int k0 = 0; k0 < K; k0 += 16) {
        const float4 a0 = *(const float4*)(Ap0 + k0);
        const float4 a1 = *(const float4*)(Ap1 + k0);
        const float4 bv = *(const float4*)(Bp  + k0);
        As[lk+0][lrow]    = a0.x; As[lk+1][lrow]    = a0.y;
        As[lk+2][lrow]    = a0.z; As[lk+3][lrow]    = a0.w;
        As[lk+0][lrow+64] = a1.x; As[lk+1][lrow+64] = a1.y;
        As[lk+2][lrow+64] = a1.z; As[lk+3][lrow+64] = a1.w;
        Bs[lk+0][lrow]    = bv.x; Bs[lk+1][lrow]    = bv.y;
        Bs[lk+2][lrow]    = bv.z; Bs[lk+3][lrow]    = bv.w;
        __syncthreads();

#pragma unroll
        for (int kk = 0; kk < 16; kk++) {
            const float4 x0 = *(const float4*)&As[kk][ty << 3];
            const float4 x1 = *(const float4*)&As[kk][(ty << 3) + 4];
            const float4 y0 = *(const float4*)&Bs[kk][tx << 2];
            const float am[8] = {x0.x, x0.y, x0.z, x0.w, x1.x, x1.y, x1.z, x1.w};
            const float bn[4] = {y0.x, y0.y, y0.z, y0.w};
#pragma unroll
            for (int i = 0; i < 8; i++)
#pragma unroll
                for (int j = 0; j < 4; j++) c[i][j] += am[i] * bn[j];
        }
        __syncthreads();
    }

    const int m0 = mb + (ty << 3);
    const int n0 = nb + (tx << 2);
#pragma unroll
    for (int i = 0; i < 8; i++) {
        float* Cr = C + (long)(m0 + i) * ldc + n0;
#pragma unroll
        for (int j = 0; j < 4; j++) {
            float v = c[i][j];
            if (EPI == 1) {           // softplus(v + bias)
                v += __ldg(&bias[n0 + j]);
                v = fmaxf(v, 0.f) + log1pf(__expf(-fabsf(v)));
            } else if (EPI == 2) {    // residual accumulate
                v += Cr[j];
            }
            Cr[j] = v;
        }
    }
}

// ---------------- causal depthwise conv (width 4) + silu ----------------
__global__ void conv_silu_kernel(const float* __restrict__ wc, const float* __restrict__ bc) {
    const int idx = blockIdx.x * blockDim.x + threadIdx.x;  // TOK*ED
    const int e   = idx & (ED - 1);
    const int tkn = idx >> 10;
    const int s   = tkn & (SEQ - 1);
    const float* xb = g_xz + (long)tkn * (2*ED) + e;   // xb = first ED cols of xz
    float acc = __ldg(&bc[e]);
    const float* w4 = wc + e * DCONV;
#pragma unroll
    for (int k = 0; k < DCONV; k++) {
        const int ss = s - (DCONV - 1) + k;
        if (ss >= 0) acc += __ldg(&w4[k]) * xb[(long)(k - (DCONV - 1)) * (2*ED)];
    }
    const float sg = 1.f / (1.f + __expf(-acc));
    g_xc[(long)tkn * ED + e] = acc * sg;
}

// ---------------- selective scan ----------------
// 4 lanes per (b,e) channel, 4 states per lane; fuses Dp*xc and silu(z) gate.
__global__ void scan_kernel(const float* __restrict__ A_log, const float* __restrict__ Dp) {
    const int g   = blockIdx.x * blockDim.x + threadIdx.x;   // 32768 threads
    const int sub = g & 3;
    const int ch  = g >> 2;
    const int e   = ch & (ED - 1);
    const int b   = ch >> 10;

    float a[4];
#pragma unroll
    for (int j = 0; j < 4; j++)
        a[j] = -__expf(__ldg(&A_log[e * DSTATE + sub * 4 + j]));
    const float dpe = __ldg(&Dp[e]);

    float h0 = 0.f, h1 = 0.f, h2 = 0.f, h3 = 0.f;
    const float* dptr  = g_delta + (long)b * SEQ * ED + e;
    const float* xptr  = g_xc    + (long)b * SEQ * ED + e;
    const float* zptr  = g_xz    + (long)b * SEQ * (2*ED) + ED + e;
    const float* bcptr = g_dbc   + (long)b * SEQ * 64 + DTRANK + sub * 4;
    float*       yptr  = g_y     + (long)b * SEQ * ED + e;

    for (int s = 0; s < SEQ; s++) {
        const float d  = dptr[(long)s * ED];
        const float xv = xptr[(long)s * ED];
        const float4 Bv = *(const float4*)(bcptr + (long)s * 64);
        const float4 Cv = *(const float4*)(bcptr + (long)s * 64 + DSTATE);
        const float dx = d * xv;
        float acc;
        h0 = __expf(d * a[0]) * h0 + dx * Bv.x; acc  = h0 * Cv.x;
        h1 = __expf(d * a[1]) * h1 + dx * Bv.y; acc += h1 * Cv.y;
        h2 = __expf(d * a[2]) * h2 + dx * Bv.z; acc += h2 * Cv.z;
        h3 = __expf(d * a[3]) * h3 + dx * Bv.w; acc += h3 * Cv.w;
        acc += __shfl_xor_sync(0xffffffffu, acc, 1);
        acc += __shfl_xor_sync(0xffffffffu, acc, 2);
        if (sub == 0) {
            const float z = zptr[(long)s * (2*ED)];
            const float y = acc + dpe * xv;
            yptr[(long)s * ED] = y * (z / (1.f + __expf(-z)));
        }
    }
}

// ---------------- final MLP head on last token ----------------
__global__ void head_kernel(const float* __restrict__ w1, const float* __restrict__ b1,
                            const float* __restrict__ w2, const float* __restrict__ b2,
                            float* __restrict__ out) {
    const int b = blockIdx.x;
    const int j = threadIdx.x;  // 64
    const float* last = g_xbuf + ((long)b * SEQ + (SEQ - 1)) * DMODEL;
    const float* wr = w1 + (long)j * DMODEL;
    float s = 0.f;
    for (int c = 0; c < DMODEL; c++) s += last[c] * __ldg(&wr[c]);
    s = fmaxf(s + __ldg(&b1[j]), 0.f);
    __shared__ float sh[64];
    sh[j] = s * __ldg(&w2[j]);
    __syncthreads();
    if (j == 0) {
        float tot = 0.f;
        for (int k = 0; k < 64; k++) tot += sh[k];
        out[b] = tot + __ldg(&b2[0]);
    }
}

// ---------------- launch ----------------
extern "C" void kernel_launch(void* const* d_in, const int* in_sizes, int n_in,
                              void* d_out, int out_size) {
    const float* x         = (const float*)d_in[0];
    const float* norm_w    = (const float*)d_in[1];
    const float* in_proj_w = (const float*)d_in[2];
    const float* conv_w    = (const float*)d_in[3];
    const float* conv_b    = (const float*)d_in[4];
    const float* x_proj_w  = (const float*)d_in[5];
    const float* dt_proj_w = (const float*)d_in[6];
    const float* dt_proj_b = (const float*)d_in[7];
    const float* A_log     = (const float*)d_in[8];
    const float* Dp        = (const float*)d_in[9];
    const float* out_proj_w= (const float*)d_in[10];
    const float* w1        = (const float*)d_in[11];
    const float* b1        = (const float*)d_in[12];
    const float* w2        = (const float*)d_in[13];
    const float* b2        = (const float*)d_in[14];

    float *p_xbuf, *p_xn, *p_xz, *p_xc, *p_dbc, *p_delta, *p_y;
    cudaGetSymbolAddress((void**)&p_xbuf,  g_xbuf);
    cudaGetSymbolAddress((void**)&p_xn,    g_xn);
    cudaGetSymbolAddress((void**)&p_xz,    g_xz);
    cudaGetSymbolAddress((void**)&p_xc,    g_xc);
    cudaGetSymbolAddress((void**)&p_dbc,   g_dbc);
    cudaGetSymbolAddress((void**)&p_delta, g_delta);
    cudaGetSymbolAddress((void**)&p_y,     g_y);

    // residual stream = input x
    cudaMemcpyAsync(p_xbuf, x, sizeof(float) * (size_t)TOK * DMODEL,
                    cudaMemcpyDeviceToDevice, 0);

    for (int l = 0; l < NLAYERS; l++) {
        // 1) rmsnorm
        rmsnorm_kernel<<<TOK, 128>>>(norm_w + (long)l * DMODEL);

        // 2) in_proj: [4096,512] x [2048,512]^T -> [4096,2048]
        {
            dim3 grid(2*ED / 64, TOK / 128);
            gemm_abt<0><<<grid, 256>>>(p_xn, DMODEL,
                                       in_proj_w + (long)l * 2*ED * DMODEL, DMODEL,
                                       p_xz, 2*ED, DMODEL, nullptr);
        }

        // 3) causal dwconv + silu -> xc
        conv_silu_kernel<<<TOK * ED / 256, 256>>>(conv_w + (long)l * ED * DCONV,
                                                  conv_b + (long)l * ED);

        // 4) x_proj: [4096,1024] x [64,1024]^T -> [4096,64]
        {
            dim3 grid(64 / 64, TOK / 128);
            gemm_abt<0><<<grid, 256>>>(p_xc, ED,
                                       x_proj_w + (long)l * 64 * ED, ED,
                                       p_dbc, 64, ED, nullptr);
        }

        // 5) dt_proj + bias + softplus: [4096,32] x [1024,32]^T -> [4096,1024]
        {
            dim3 grid(ED / 64, TOK / 128);
            gemm_abt<1><<<grid, 256>>>(p_dbc, 64,
                                       dt_proj_w + (long)l * ED * DTRANK, DTRANK,
                                       p_delta, ED, DTRANK,
                                       dt_proj_b + (long)l * ED);
        }

        // 6) selective scan (fuses Dp*xc and silu(z) gate)
        scan_kernel<<<(BATCH * ED * 4) / 256, 256>>>(A_log + (long)l * ED * DSTATE,
                                                     Dp + (long)l * ED);

        // 7) out_proj + residual: [4096,1024] x [512,1024]^T += xbuf
        {
            dim3 grid(DMODEL / 64, TOK / 128);
            gemm_abt<2><<<grid, 256>>>(p_y, ED,
                                       out_proj_w + (long)l * DMODEL * ED, ED,
                                       p_xbuf, DMODEL, ED, nullptr);
        }
    }

    // final MLP head
    head_kernel<<<BATCH, 64>>>(w1, b1, w2, b2, (float*)d_out);
}

// round 6
// speedup vs baseline: 1.1282x; 1.1282x over previous
#include <cuda_runtime.h>
#include <cuda_bf16.h>
#include <cstdint>

// ---------------- problem constants ----------------
#define NLAYERS 4
#define BATCH   8
#define SEQ     512
#define DMODEL  512
#define ED      1024
#define DSTATE  16
#define DTRANK  32
#define DCONV   4
#define TOK     (BATCH*SEQ)   // 4096

typedef __nv_bfloat16 bf16;

// ---------------- scratch (device globals; no allocation) ----------------
__device__ __align__(16) float g_xbuf [TOK*DMODEL];     // residual stream
__device__ __align__(16) float g_xz   [TOK*2*ED];       // in_proj out (xb|z)
__device__ __align__(16) float g_xc   [TOK*ED];         // conv+silu (fp32 for scan)
__device__ __align__(16) float g_dbc  [TOK*64];         // x_proj out (dt|B|C)
__device__ __align__(16) float g_delta[TOK*ED];         // softplus(dt_proj)

// bf16 split activations
__device__ __align__(16) bf16 g_xn_h[TOK*DMODEL],  g_xn_l[TOK*DMODEL];
__device__ __align__(16) bf16 g_xc_h[TOK*ED],      g_xc_l[TOK*ED];
__device__ __align__(16) bf16 g_y_h [TOK*ED],      g_y_l [TOK*ED];
__device__ __align__(16) bf16 g_dt_h[TOK*64],      g_dt_l[TOK*64];   // padded K=64

// bf16 split weights
__device__ __align__(16) bf16 g_inw_h[NLAYERS*2*ED*DMODEL], g_inw_l[NLAYERS*2*ED*DMODEL];
__device__ __align__(16) bf16 g_outw_h[NLAYERS*DMODEL*ED],  g_outw_l[NLAYERS*DMODEL*ED];
__device__ __align__(16) bf16 g_xpw_h[NLAYERS*64*ED],       g_xpw_l[NLAYERS*64*ED];
__device__ __align__(16) bf16 g_dtw_h[NLAYERS*ED*64],       g_dtw_l[NLAYERS*ED*64]; // padded

// ---------------- HMMA m16n8k16 bf16 ----------------
__device__ __forceinline__ void mma16816(float* c, const uint32_t* a, const uint32_t* b) {
    asm volatile(
        "mma.sync.aligned.m16n8k16.row.col.f32.bf16.bf16.f32 "
        "{%0,%1,%2,%3}, {%4,%5,%6,%7}, {%8,%9}, {%0,%1,%2,%3};"
        : "+f"(c[0]), "+f"(c[1]), "+f"(c[2]), "+f"(c[3])
        : "r"(a[0]), "r"(a[1]), "r"(a[2]), "r"(a[3]), "r"(b[0]), "r"(b[1]));
}

// ---------------- split-bf16 HMMA GEMM ----------------
// C[M=4096, N](fp32) (+=) [Ah+Al][M,K] * [Bh+Bl][N,K]^T   (both row-major, k-contiguous)
// CTA tile 128x64, K chunk 32. 256 threads = 8 warps (4 m x 2 n), warp tile 32x32.
// EPI: 0 = store, 1 = softplus(acc + bias[n]), 2 = C += acc
#define SPAD 40   // smem row stride in bf16 (padded; 80B rows keep frag loads conflict-free, 16B-aligned)

template<int EPI>
__global__ void __launch_bounds__(256) hmma_gemm(
    const bf16* __restrict__ Ah, const bf16* __restrict__ Al, int lda,
    const bf16* __restrict__ Bh, const bf16* __restrict__ Bl,
    float* __restrict__ C, int ldc, int K, const float* __restrict__ bias)
{
    __shared__ bf16 As_h[128*SPAD], As_l[128*SPAD];
    __shared__ bf16 Bs_h[64*SPAD],  Bs_l[64*SPAD];

    const int tid = threadIdx.x;
    const int wid = tid >> 5, lid = tid & 31;
    const int g = lid >> 2, t = lid & 3;           // mma fragment coords
    const int wm = wid >> 1, wn = wid & 1;         // warp tile coords
    const int mb = blockIdx.y * 128;
    const int nb = blockIdx.x * 64;

    float c[2][4][4];
#pragma unroll
    for (int mi = 0; mi < 2; mi++)
#pragma unroll
        for (int ni = 0; ni < 4; ni++)
#pragma unroll
            for (int k = 0; k < 4; k++) c[mi][ni][k] = 0.f;

    for (int k0 = 0; k0 < K; k0 += 32) {
        // ---- load chunk to smem (uint4 = 8 bf16) ----
#pragma unroll
        for (int i = 0; i < 2; i++) {                    // A: 128 rows x 32 k = 512 uint4
            const int idx = tid + i*256;
            const int row = idx >> 2, seg = idx & 3;
            const long gi = (long)(mb + row) * lda + k0 + seg*8;
            *(uint4*)&As_h[row*SPAD + seg*8] = *(const uint4*)(Ah + gi);
            *(uint4*)&As_l[row*SPAD + seg*8] = *(const uint4*)(Al + gi);
        }
        {                                                // B: 64 rows x 32 k = 256 uint4
            const int row = tid >> 2, seg = tid & 3;
            const long gi = (long)(nb + row) * K + k0 + seg*8;
            *(uint4*)&Bs_h[row*SPAD + seg*8] = *(const uint4*)(Bh + gi);
            *(uint4*)&Bs_l[row*SPAD + seg*8] = *(const uint4*)(Bl + gi);
        }
        __syncthreads();

#pragma unroll
        for (int kk = 0; kk < 2; kk++) {
            const int kb = kk * 16;
            uint32_t ah[2][4], al[2][4], bh[4][2], bl[4][2];
#pragma unroll
            for (int mi = 0; mi < 2; mi++) {
                const int r0 = (wm*32 + mi*16 + g) * SPAD + kb + 2*t;
                const int r8 = r0 + 8*SPAD;
                ah[mi][0] = *(const uint32_t*)&As_h[r0];
                ah[mi][1] = *(const uint32_t*)&As_h[r8];
                ah[mi][2] = *(const uint32_t*)&As_h[r0 + 8];
                ah[mi][3] = *(const uint32_t*)&As_h[r8 + 8];
                al[mi][0] = *(const uint32_t*)&As_l[r0];
                al[mi][1] = *(const uint32_t*)&As_l[r8];
                al[mi][2] = *(const uint32_t*)&As_l[r0 + 8];
                al[mi][3] = *(const uint32_t*)&As_l[r8 + 8];
            }
#pragma unroll
            for (int ni = 0; ni < 4; ni++) {
                const int r = (wn*32 + ni*8 + g) * SPAD + kb + 2*t;
                bh[ni][0] = *(const uint32_t*)&Bs_h[r];
                bh[ni][1] = *(const uint32_t*)&Bs_h[r + 8];
                bl[ni][0] = *(const uint32_t*)&Bs_l[r];
                bl[ni][1] = *(const uint32_t*)&Bs_l[r + 8];
            }
#pragma unroll
            for (int mi = 0; mi < 2; mi++)
#pragma unroll
                for (int ni = 0; ni < 4; ni++) {
                    mma16816(c[mi][ni], ah[mi], bh[ni]);
                    mma16816(c[mi][ni], ah[mi], bl[ni]);
                    mma16816(c[mi][ni], al[mi], bh[ni]);
                }
        }
        __syncthreads();
    }

    // ---- epilogue: float2 per (row, colpair) ----
#pragma unroll
    for (int mi = 0; mi < 2; mi++) {
        const int row0 = mb + wm*32 + mi*16 + g;
#pragma unroll
        for (int ni = 0; ni < 4; ni++) {
            const int col = nb + wn*32 + ni*8 + 2*t;
#pragma unroll
            for (int h = 0; h < 2; h++) {           // h=0: rows g, h=1: rows g+8
                float v0 = c[mi][ni][2*h + 0];
                float v1 = c[mi][ni][2*h + 1];
                float* Cr = C + (long)(row0 + h*8) * ldc + col;
                if (EPI == 1) {
                    v0 += __ldg(&bias[col + 0]);
                    v1 += __ldg(&bias[col + 1]);
                    v0 = fmaxf(v0, 0.f) + log1pf(__expf(-fabsf(v0)));
                    v1 = fmaxf(v1, 0.f) + log1pf(__expf(-fabsf(v1)));
                } else if (EPI == 2) {
                    const float2 old = *(const float2*)Cr;
                    v0 += old.x; v1 += old.y;
                }
                const float2 o = make_float2(v0, v1);
                *(float2*)Cr = o;
            }
        }
    }
}

// ---------------- fp32 -> bf16 hi/lo split ----------------
__global__ void cvt_split(const float* __restrict__ s, bf16* __restrict__ h,
                          bf16* __restrict__ l, int n) {
    const int i = blockIdx.x * 256 + threadIdx.x;
    if (i < n) {
        const float v = s[i];
        const bf16 hv = __float2bfloat16(v);
        h[i] = hv;
        l[i] = __float2bfloat16(v - __bfloat162float(hv));
    }
}
// dt_proj weights: [L*ED, 32] -> padded [L*ED, 64]
__global__ void cvt_dtw(const float* __restrict__ s, bf16* __restrict__ h, bf16* __restrict__ l) {
    const int i = blockIdx.x * 256 + threadIdx.x;   // NLAYERS*ED*64
    const int k = i & 63, r = i >> 6;
    const float v = (k < DTRANK) ? s[r * DTRANK + k] : 0.f;
    const bf16 hv = __float2bfloat16(v);
    h[i] = hv;
    l[i] = __float2bfloat16(v - __bfloat162float(hv));
}
// dt activation: first 32 cols of dbc -> padded [4096, 64]
__global__ void cvt_dt() {
    const int i = blockIdx.x * 256 + threadIdx.x;   // TOK*64
    const int k = i & 63;
    const float v = (k < DTRANK) ? g_dbc[i] : 0.f;
    const bf16 hv = __float2bfloat16(v);
    g_dt_h[i] = hv;
    g_dt_l[i] = __float2bfloat16(v - __bfloat162float(hv));
}

// ---------------- rmsnorm: writes bf16 hi/lo ----------------
__global__ void rmsnorm_kernel(const float* __restrict__ w) {
    const int tkn = blockIdx.x;
    const float* xr = g_xbuf + (long)tkn * DMODEL;
    const int t = threadIdx.x;   // 128
    float v[4];
    float s = 0.f;
#pragma unroll
    for (int i = 0; i < 4; i++) { v[i] = xr[t + i*128]; s += v[i]*v[i]; }
#pragma unroll
    for (int off = 16; off; off >>= 1) s += __shfl_xor_sync(0xffffffffu, s, off);
    __shared__ float sh[4];
    if ((t & 31) == 0) sh[t >> 5] = s;
    __syncthreads();
    const float scale = rsqrtf((sh[0]+sh[1]+sh[2]+sh[3]) * (1.0f/DMODEL) + 1e-5f);
#pragma unroll
    for (int i = 0; i < 4; i++) {
        const float o = v[i] * scale * __ldg(&w[t + i*128]);
        const long idx = (long)tkn * DMODEL + t + i*128;
        const bf16 hv = __float2bfloat16(o);
        g_xn_h[idx] = hv;
        g_xn_l[idx] = __float2bfloat16(o - __bfloat162float(hv));
    }
}

// ---------------- causal dwconv(4) + silu: fp32 + bf16 hi/lo ----------------
__global__ void conv_silu_kernel(const float* __restrict__ wc, const float* __restrict__ bc) {
    const int idx = blockIdx.x * blockDim.x + threadIdx.x;  // TOK*ED
    const int e   = idx & (ED - 1);
    const int tkn = idx >> 10;
    const int s   = tkn & (SEQ - 1);
    const float* xb = g_xz + (long)tkn * (2*ED) + e;
    float acc = __ldg(&bc[e]);
    const float* w4 = wc + e * DCONV;
#pragma unroll
    for (int k = 0; k < DCONV; k++) {
        const int ss = s - (DCONV - 1) + k;
        if (ss >= 0) acc += __ldg(&w4[k]) * xb[(long)(k - (DCONV - 1)) * (2*ED)];
    }
    const float v = acc / (1.f + __expf(-acc));
    const long o = (long)tkn * ED + e;
    g_xc[o] = v;
    const bf16 hv = __float2bfloat16(v);
    g_xc_h[o] = hv;
    g_xc_l[o] = __float2bfloat16(v - __bfloat162float(hv));
}

// ---------------- selective scan: writes y as bf16 hi/lo ----------------
__global__ void scan_kernel(const float* __restrict__ A_log, const float* __restrict__ Dp) {
    const int g   = blockIdx.x * blockDim.x + threadIdx.x;
    const int sub = g & 3;
    const int ch  = g >> 2;
    const int e   = ch & (ED - 1);
    const int b   = ch >> 10;

    float a[4];
#pragma unroll
    for (int j = 0; j < 4; j++)
        a[j] = -__expf(__ldg(&A_log[e * DSTATE + sub * 4 + j]));
    const float dpe = __ldg(&Dp[e]);

    float h0 = 0.f, h1 = 0.f, h2 = 0.f, h3 = 0.f;
    const float* dptr  = g_delta + (long)b * SEQ * ED + e;
    const float* xptr  = g_xc    + (long)b * SEQ * ED + e;
    const float* zptr  = g_xz    + (long)b * SEQ * (2*ED) + ED + e;
    const float* bcptr = g_dbc   + (long)b * SEQ * 64 + DTRANK + sub * 4;
    const long   ybase = (long)b * SEQ * ED + e;

    for (int s = 0; s < SEQ; s++) {
        const float d  = dptr[(long)s * ED];
        const float xv = xptr[(long)s * ED];
        const float4 Bv = *(const float4*)(bcptr + (long)s * 64);
        const float4 Cv = *(const float4*)(bcptr + (long)s * 64 + DSTATE);
        const float dx = d * xv;
        float acc;
        h0 = __expf(d * a[0]) * h0 + dx * Bv.x; acc  = h0 * Cv.x;
        h1 = __expf(d * a[1]) * h1 + dx * Bv.y; acc += h1 * Cv.y;
        h2 = __expf(d * a[2]) * h2 + dx * Bv.z; acc += h2 * Cv.z;
        h3 = __expf(d * a[3]) * h3 + dx * Bv.w; acc += h3 * Cv.w;
        acc += __shfl_xor_sync(0xffffffffu, acc, 1);
        acc += __shfl_xor_sync(0xffffffffu, acc, 2);
        if (sub == 0) {
            const float z = zptr[(long)s * (2*ED)];
            const float y = (acc + dpe * xv) * (z / (1.f + __expf(-z)));
            const bf16 hv = __float2bfloat16(y);
            g_y_h[ybase + (long)s * ED] = hv;
            g_y_l[ybase + (long)s * ED] = __float2bfloat16(y - __bfloat162float(hv));
        }
    }
}

// ---------------- final MLP head ----------------
__global__ void head_kernel(const float* __restrict__ w1, const float* __restrict__ b1,
                            const float* __restrict__ w2, const float* __restrict__ b2,
                            float* __restrict__ out) {
    const int b = blockIdx.x;
    const int j = threadIdx.x;  // 64
    const float* last = g_xbuf + ((long)b * SEQ + (SEQ - 1)) * DMODEL;
    const float* wr = w1 + (long)j * DMODEL;
    float s = 0.f;
    for (int c = 0; c < DMODEL; c++) s += last[c] * __ldg(&wr[c]);
    s = fmaxf(s + __ldg(&b1[j]), 0.f);
    __shared__ float sh[64];
    sh[j] = s * __ldg(&w2[j]);
    __syncthreads();
    if (j == 0) {
        float tot = 0.f;
        for (int k = 0; k < 64; k++) tot += sh[k];
        out[b] = tot + __ldg(&b2[0]);
    }
}

// ---------------- launch ----------------
extern "C" void kernel_launch(void* const* d_in, const int* in_sizes, int n_in,
                              void* d_out, int out_size) {
    const float* x         = (const float*)d_in[0];
    const float* norm_w    = (const float*)d_in[1];
    const float* in_proj_w = (const float*)d_in[2];
    const float* conv_w    = (const float*)d_in[3];
    const float* conv_b    = (const float*)d_in[4];
    const float* x_proj_w  = (const float*)d_in[5];
    const float* dt_proj_w = (const float*)d_in[6];
    const float* dt_proj_b = (const float*)d_in[7];
    const float* A_log     = (const float*)d_in[8];
    const float* Dp        = (const float*)d_in[9];
    const float* out_proj_w= (const float*)d_in[10];
    const float* w1        = (const float*)d_in[11];
    const float* b1        = (const float*)d_in[12];
    const float* w2        = (const float*)d_in[13];
    const float* b2        = (const float*)d_in[14];

    float *p_xbuf, *p_xz, *p_dbc, *p_delta;
    cudaGetSymbolAddress((void**)&p_xbuf,  g_xbuf);
    cudaGetSymbolAddress((void**)&p_xz,    g_xz);
    cudaGetSymbolAddress((void**)&p_dbc,   g_dbc);
    cudaGetSymbolAddress((void**)&p_delta, g_delta);

    bf16 *p_xn_h, *p_xn_l, *p_xc_h, *p_xc_l, *p_y_h, *p_y_l, *p_dt_h, *p_dt_l;
    bf16 *p_inw_h, *p_inw_l, *p_outw_h, *p_outw_l, *p_xpw_h, *p_xpw_l, *p_dtw_h, *p_dtw_l;
    cudaGetSymbolAddress((void**)&p_xn_h, g_xn_h);   cudaGetSymbolAddress((void**)&p_xn_l, g_xn_l);
    cudaGetSymbolAddress((void**)&p_xc_h, g_xc_h);   cudaGetSymbolAddress((void**)&p_xc_l, g_xc_l);
    cudaGetSymbolAddress((void**)&p_y_h,  g_y_h);    cudaGetSymbolAddress((void**)&p_y_l,  g_y_l);
    cudaGetSymbolAddress((void**)&p_dt_h, g_dt_h);   cudaGetSymbolAddress((void**)&p_dt_l, g_dt_l);
    cudaGetSymbolAddress((void**)&p_inw_h, g_inw_h); cudaGetSymbolAddress((void**)&p_inw_l, g_inw_l);
    cudaGetSymbolAddress((void**)&p_outw_h, g_outw_h); cudaGetSymbolAddress((void**)&p_outw_l, g_outw_l);
    cudaGetSymbolAddress((void**)&p_xpw_h, g_xpw_h); cudaGetSymbolAddress((void**)&p_xpw_l, g_xpw_l);
    cudaGetSymbolAddress((void**)&p_dtw_h, g_dtw_h); cudaGetSymbolAddress((void**)&p_dtw_l, g_dtw_l);

    // residual stream = input x
    cudaMemcpyAsync(p_xbuf, x, sizeof(float) * (size_t)TOK * DMODEL,
                    cudaMemcpyDeviceToDevice, 0);

    // ---- weight conversion ----
    {
        const int n_in_w  = NLAYERS * 2*ED * DMODEL;
        const int n_out_w = NLAYERS * DMODEL * ED;
        const int n_xp_w  = NLAYERS * 64 * ED;
        const int n_dt_w  = NLAYERS * ED * 64;
        cvt_split<<<(n_in_w  + 255)/256, 256>>>(in_proj_w,  p_inw_h,  p_inw_l,  n_in_w);
        cvt_split<<<(n_out_w + 255)/256, 256>>>(out_proj_w, p_outw_h, p_outw_l, n_out_w);
        cvt_split<<<(n_xp_w  + 255)/256, 256>>>(x_proj_w,   p_xpw_h,  p_xpw_l,  n_xp_w);
        cvt_dtw  <<<(n_dt_w  + 255)/256, 256>>>(dt_proj_w,  p_dtw_h,  p_dtw_l);
    }

    for (int l = 0; l < NLAYERS; l++) {
        // 1) rmsnorm -> xn hi/lo
        rmsnorm_kernel<<<TOK, 128>>>(norm_w + (long)l * DMODEL);

        // 2) in_proj: [4096,512]x[2048,512]^T -> xz fp32
        hmma_gemm<0><<<dim3(2*ED/64, TOK/128), 256>>>(
            p_xn_h, p_xn_l, DMODEL,
            p_inw_h + (long)l * 2*ED * DMODEL, p_inw_l + (long)l * 2*ED * DMODEL,
            p_xz, 2*ED, DMODEL, nullptr);

        // 3) conv + silu -> xc fp32 + hi/lo
        conv_silu_kernel<<<TOK * ED / 256, 256>>>(conv_w + (long)l * ED * DCONV,
                                                  conv_b + (long)l * ED);

        // 4) x_proj: [4096,1024]x[64,1024]^T -> dbc fp32
        hmma_gemm<0><<<dim3(1, TOK/128), 256>>>(
            p_xc_h, p_xc_l, ED,
            p_xpw_h + (long)l * 64 * ED, p_xpw_l + (long)l * 64 * ED,
            p_dbc, 64, ED, nullptr);

        // 5) dt split (padded K=64)
        cvt_dt<<<TOK * 64 / 256, 256>>>();

        // 6) dt_proj + softplus: [4096,64]x[1024,64]^T -> delta
        hmma_gemm<1><<<dim3(ED/64, TOK/128), 256>>>(
            p_dt_h, p_dt_l, 64,
            p_dtw_h + (long)l * ED * 64, p_dtw_l + (long)l * ED * 64,
            p_delta, ED, 64, dt_proj_b + (long)l * ED);

        // 7) scan -> y hi/lo
        scan_kernel<<<(BATCH * ED * 4) / 256, 256>>>(A_log + (long)l * ED * DSTATE,
                                                     Dp + (long)l * ED);

        // 8) out_proj + residual: [4096,1024]x[512,1024]^T += xbuf
        hmma_gemm<2><<<dim3(DMODEL/64, TOK/128), 256>>>(
            p_y_h, p_y_l, ED,
            p_outw_h + (long)l * DMODEL * ED, p_outw_l + (long)l * DMODEL * ED,
            p_xbuf, DMODEL, ED, nullptr);
    }

    head_kernel<<<BATCH, 64>>>(w1, b1, w2, b2, (float*)d_out);
}

// round 7
// speedup vs baseline: 1.2203x; 1.0817x over previous
#include <cuda_runtime.h>
#include <cuda_bf16.h>
#include <cstdint>

// ---------------- problem constants ----------------
#define NLAYERS 4
#define BATCH   8
#define SEQ     512
#define DMODEL  512
#define ED      1024
#define DSTATE  16
#define DTRANK  32
#define DCONV   4
#define TOK     (BATCH*SEQ)   // 4096

typedef __nv_bfloat16 bf16;

// ---------------- scratch (device globals; no allocation) ----------------
__device__ __align__(16) float g_xbuf [TOK*DMODEL];     // residual stream
__device__ __align__(16) float g_xz   [TOK*2*ED];       // in_proj out (xb|z)
__device__ __align__(16) float g_xc   [TOK*ED];         // conv+silu (fp32 for scan)
__device__ __align__(16) float g_dbc  [TOK*64];         // x_proj out (dt|B|C)
__device__ __align__(16) float g_delta[TOK*ED];         // softplus(dt_proj)

// bf16 split activations
__device__ __align__(16) bf16 g_xn_h[TOK*DMODEL],  g_xn_l[TOK*DMODEL];
__device__ __align__(16) bf16 g_xc_h[TOK*ED],      g_xc_l[TOK*ED];
__device__ __align__(16) bf16 g_y_h [TOK*ED],      g_y_l [TOK*ED];
__device__ __align__(16) bf16 g_dt_h[TOK*DTRANK],  g_dt_l[TOK*DTRANK];   // K=32

// bf16 split weights
__device__ __align__(16) bf16 g_inw_h[NLAYERS*2*ED*DMODEL], g_inw_l[NLAYERS*2*ED*DMODEL];
__device__ __align__(16) bf16 g_outw_h[NLAYERS*DMODEL*ED],  g_outw_l[NLAYERS*DMODEL*ED];
__device__ __align__(16) bf16 g_xpw_h[NLAYERS*64*ED],       g_xpw_l[NLAYERS*64*ED];
__device__ __align__(16) bf16 g_dtw_h[NLAYERS*ED*DTRANK],   g_dtw_l[NLAYERS*ED*DTRANK];

// ---------------- HMMA m16n8k16 bf16 ----------------
__device__ __forceinline__ void mma16816(float* c, const uint32_t* a, const uint32_t* b) {
    asm volatile(
        "mma.sync.aligned.m16n8k16.row.col.f32.bf16.bf16.f32 "
        "{%0,%1,%2,%3}, {%4,%5,%6,%7}, {%8,%9}, {%0,%1,%2,%3};"
        : "+f"(c[0]), "+f"(c[1]), "+f"(c[2]), "+f"(c[3])
        : "r"(a[0]), "r"(a[1]), "r"(a[2]), "r"(a[3]), "r"(b[0]), "r"(b[1]));
}

__device__ __forceinline__ void cp16(uint32_t smem_dst, const void* gsrc) {
    asm volatile("cp.async.cg.shared.global [%0], [%1], 16;" :: "r"(smem_dst), "l"(gsrc));
}
#define CP_COMMIT() asm volatile("cp.async.commit_group;" ::: "memory")
#define CP_WAIT(N)  asm volatile("cp.async.wait_group %0;" :: "n"(N) : "memory")

// ---------------- split-bf16 HMMA GEMM, cp.async double-buffered ----------------
// C[M=4096, N](fp32) (+=) [Ah+Al][M,K] * [Bh+Bl][N,K]^T  (row-major, k-contiguous)
// CTA tile 128x64, K chunk 32. 256 threads = 8 warps (4m x 2n), warp tile 32x32.
// EPI: 0 store, 1 softplus(acc+bias), 2 residual +=, 3 store + dt hi/lo split
#define SPAD 40                      // smem row stride (bf16); 80B rows, conflict-free
#define ASZ  (128*SPAD)
#define BSZ  (64*SPAD)
#define STG  (2*ASZ + 2*BSZ)         // bf16 elems per stage (15360 -> 30720 B)
#define GSMEM (2*STG*2)              // total dynamic smem bytes (61440)

template<int EPI>
__global__ void __launch_bounds__(256) hmma_gemm(
    const bf16* __restrict__ Ah, const bf16* __restrict__ Al, int lda,
    const bf16* __restrict__ Bh, const bf16* __restrict__ Bl,
    float* __restrict__ C, int ldc, int K, const float* __restrict__ bias)
{
    extern __shared__ bf16 sm[];

    const int tid = threadIdx.x;
    const int wid = tid >> 5, lid = tid & 31;
    const int g = lid >> 2, t = lid & 3;
    const int wm = wid >> 1, wn = wid & 1;
    const int mb = blockIdx.y * 128;
    const int nb = blockIdx.x * 64;

    // per-thread load coords
    const int arow = tid >> 2, aseg = tid & 3;        // A: rows via 2 iters
    const int brow = tid >> 2, bseg = tid & 3;        // B: 64 rows x 4 segs

    const uint32_t smbase = (uint32_t)__cvta_generic_to_shared(sm);

    float c[2][4][4];
#pragma unroll
    for (int mi = 0; mi < 2; mi++)
#pragma unroll
        for (int ni = 0; ni < 4; ni++)
#pragma unroll
            for (int k = 0; k < 4; k++) c[mi][ni][k] = 0.f;

    const int nch = K >> 5;

    // ---- stage loader ----
    auto load_stage = [&](int ch, int st) {
        const int k0 = ch << 5;
        const uint32_t s0 = smbase + (uint32_t)(st * STG) * 2u;
#pragma unroll
        for (int i = 0; i < 2; i++) {
            const int row = arow + i*64;
            const uint32_t d = s0 + (uint32_t)(row*SPAD + aseg*8) * 2u;
            const long gi = (long)(mb + row) * lda + k0 + aseg*8;
            cp16(d,            Ah + gi);
            cp16(d + ASZ*2u,   Al + gi);
        }
        {
            const uint32_t d = s0 + (uint32_t)(2*ASZ + brow*SPAD + bseg*8) * 2u;
            const long gi = (long)(nb + brow) * K + k0 + bseg*8;
            cp16(d,            Bh + gi);
            cp16(d + BSZ*2u,   Bl + gi);
        }
    };

    load_stage(0, 0);
    CP_COMMIT();

    for (int ch = 0; ch < nch; ch++) {
        const int st = ch & 1;
        if (ch + 1 < nch) {
            load_stage(ch + 1, st ^ 1);
            CP_COMMIT();
            CP_WAIT(1);
        } else {
            CP_WAIT(0);
        }
        __syncthreads();

        const bf16* As_h = sm + st*STG;
        const bf16* As_l = As_h + ASZ;
        const bf16* Bs_h = As_h + 2*ASZ;
        const bf16* Bs_l = Bs_h + BSZ;

#pragma unroll
        for (int kk = 0; kk < 2; kk++) {
            const int kb = kk * 16;
            uint32_t ah[2][4], al[2][4], bh[4][2], bl[4][2];
#pragma unroll
            for (int mi = 0; mi < 2; mi++) {
                const int r0 = (wm*32 + mi*16 + g) * SPAD + kb + 2*t;
                const int r8 = r0 + 8*SPAD;
                ah[mi][0] = *(const uint32_t*)&As_h[r0];
                ah[mi][1] = *(const uint32_t*)&As_h[r8];
                ah[mi][2] = *(const uint32_t*)&As_h[r0 + 8];
                ah[mi][3] = *(const uint32_t*)&As_h[r8 + 8];
                al[mi][0] = *(const uint32_t*)&As_l[r0];
                al[mi][1] = *(const uint32_t*)&As_l[r8];
                al[mi][2] = *(const uint32_t*)&As_l[r0 + 8];
                al[mi][3] = *(const uint32_t*)&As_l[r8 + 8];
            }
#pragma unroll
            for (int ni = 0; ni < 4; ni++) {
                const int r = (wn*32 + ni*8 + g) * SPAD + kb + 2*t;
                bh[ni][0] = *(const uint32_t*)&Bs_h[r];
                bh[ni][1] = *(const uint32_t*)&Bs_h[r + 8];
                bl[ni][0] = *(const uint32_t*)&Bs_l[r];
                bl[ni][1] = *(const uint32_t*)&Bs_l[r + 8];
            }
#pragma unroll
            for (int mi = 0; mi < 2; mi++)
#pragma unroll
                for (int ni = 0; ni < 4; ni++) {
                    mma16816(c[mi][ni], ah[mi], bh[ni]);
                    mma16816(c[mi][ni], ah[mi], bl[ni]);
                    mma16816(c[mi][ni], al[mi], bh[ni]);
                }
        }
        __syncthreads();
    }

    // ---- epilogue ----
#pragma unroll
    for (int mi = 0; mi < 2; mi++) {
        const int row0 = mb + wm*32 + mi*16 + g;
#pragma unroll
        for (int ni = 0; ni < 4; ni++) {
            const int col = nb + wn*32 + ni*8 + 2*t;
#pragma unroll
            for (int h = 0; h < 2; h++) {
                float v0 = c[mi][ni][2*h + 0];
                float v1 = c[mi][ni][2*h + 1];
                const int row = row0 + h*8;
                float* Cr = C + (long)row * ldc + col;
                if (EPI == 1) {
                    v0 += __ldg(&bias[col + 0]);
                    v1 += __ldg(&bias[col + 1]);
                    v0 = fmaxf(v0, 0.f) + log1pf(__expf(-fabsf(v0)));
                    v1 = fmaxf(v1, 0.f) + log1pf(__expf(-fabsf(v1)));
                } else if (EPI == 2) {
                    const float2 old = *(const float2*)Cr;
                    v0 += old.x; v1 += old.y;
                }
                *(float2*)Cr = make_float2(v0, v1);
                if (EPI == 3 && col < DTRANK) {     // fused dt hi/lo split
                    const long di = (long)row * DTRANK + col;
                    const bf16 h0 = __float2bfloat16(v0);
                    const bf16 h1 = __float2bfloat16(v1);
                    g_dt_h[di]   = h0;
                    g_dt_l[di]   = __float2bfloat16(v0 - __bfloat162float(h0));
                    g_dt_h[di+1] = h1;
                    g_dt_l[di+1] = __float2bfloat16(v1 - __bfloat162float(h1));
                }
            }
        }
    }
}

// ---------------- fp32 -> bf16 hi/lo split ----------------
__global__ void cvt_split(const float* __restrict__ s, bf16* __restrict__ h,
                          bf16* __restrict__ l, int n) {
    const int i = blockIdx.x * 256 + threadIdx.x;
    if (i < n) {
        const float v = s[i];
        const bf16 hv = __float2bfloat16(v);
        h[i] = hv;
        l[i] = __float2bfloat16(v - __bfloat162float(hv));
    }
}

// ---------------- rmsnorm: writes bf16 hi/lo ----------------
__global__ void rmsnorm_kernel(const float* __restrict__ w) {
    const int tkn = blockIdx.x;
    const float* xr = g_xbuf + (long)tkn * DMODEL;
    const int t = threadIdx.x;   // 128
    float v[4];
    float s = 0.f;
#pragma unroll
    for (int i = 0; i < 4; i++) { v[i] = xr[t + i*128]; s += v[i]*v[i]; }
#pragma unroll
    for (int off = 16; off; off >>= 1) s += __shfl_xor_sync(0xffffffffu, s, off);
    __shared__ float sh[4];
    if ((t & 31) == 0) sh[t >> 5] = s;
    __syncthreads();
    const float scale = rsqrtf((sh[0]+sh[1]+sh[2]+sh[3]) * (1.0f/DMODEL) + 1e-5f);
#pragma unroll
    for (int i = 0; i < 4; i++) {
        const float o = v[i] * scale * __ldg(&w[t + i*128]);
        const long idx = (long)tkn * DMODEL + t + i*128;
        const bf16 hv = __float2bfloat16(o);
        g_xn_h[idx] = hv;
        g_xn_l[idx] = __float2bfloat16(o - __bfloat162float(hv));
    }
}

// ---------------- causal dwconv(4) + silu: fp32 + bf16 hi/lo ----------------
__global__ void conv_silu_kernel(const float* __restrict__ wc, const float* __restrict__ bc) {
    const int idx = blockIdx.x * blockDim.x + threadIdx.x;  // TOK*ED
    const int e   = idx & (ED - 1);
    const int tkn = idx >> 10;
    const int s   = tkn & (SEQ - 1);
    const float* xb = g_xz + (long)tkn * (2*ED) + e;
    float acc = __ldg(&bc[e]);
    const float* w4 = wc + e * DCONV;
#pragma unroll
    for (int k = 0; k < DCONV; k++) {
        const int ss = s - (DCONV - 1) + k;
        if (ss >= 0) acc += __ldg(&w4[k]) * xb[(long)(k - (DCONV - 1)) * (2*ED)];
    }
    const float v = acc / (1.f + __expf(-acc));
    const long o = (long)tkn * ED + e;
    g_xc[o] = v;
    const bf16 hv = __float2bfloat16(v);
    g_xc_h[o] = hv;
    g_xc_l[o] = __float2bfloat16(v - __bfloat162float(hv));
}

// ---------------- selective scan: writes y as bf16 hi/lo ----------------
__global__ void scan_kernel(const float* __restrict__ A_log, const float* __restrict__ Dp) {
    const int g   = blockIdx.x * blockDim.x + threadIdx.x;
    const int sub = g & 3;
    const int ch  = g >> 2;
    const int e   = ch & (ED - 1);
    const int b   = ch >> 10;

    float a[4];
#pragma unroll
    for (int j = 0; j < 4; j++)
        a[j] = -__expf(__ldg(&A_log[e * DSTATE + sub * 4 + j]));
    const float dpe = __ldg(&Dp[e]);

    float h0 = 0.f, h1 = 0.f, h2 = 0.f, h3 = 0.f;
    const float* dptr  = g_delta + (long)b * SEQ * ED + e;
    const float* xptr  = g_xc    + (long)b * SEQ * ED + e;
    const float* zptr  = g_xz    + (long)b * SEQ * (2*ED) + ED + e;
    const float* bcptr = g_dbc   + (long)b * SEQ * 64 + DTRANK + sub * 4;
    const long   ybase = (long)b * SEQ * ED + e;

    for (int s = 0; s < SEQ; s++) {
        const float d  = dptr[(long)s * ED];
        const float xv = xptr[(long)s * ED];
        const float4 Bv = *(const float4*)(bcptr + (long)s * 64);
        const float4 Cv = *(const float4*)(bcptr + (long)s * 64 + DSTATE);
        const float dx = d * xv;
        float acc;
        h0 = __expf(d * a[0]) * h0 + dx * Bv.x; acc  = h0 * Cv.x;
        h1 = __expf(d * a[1]) * h1 + dx * Bv.y; acc += h1 * Cv.y;
        h2 = __expf(d * a[2]) * h2 + dx * Bv.z; acc += h2 * Cv.z;
        h3 = __expf(d * a[3]) * h3 + dx * Bv.w; acc += h3 * Cv.w;
        acc += __shfl_xor_sync(0xffffffffu, acc, 1);
        acc += __shfl_xor_sync(0xffffffffu, acc, 2);
        if (sub == 0) {
            const float z = zptr[(long)s * (2*ED)];
            const float y = (acc + dpe * xv) * (z / (1.f + __expf(-z)));
            const bf16 hv = __float2bfloat16(y);
            g_y_h[ybase + (long)s * ED] = hv;
            g_y_l[ybase + (long)s * ED] = __float2bfloat16(y - __bfloat162float(hv));
        }
    }
}

// ---------------- final MLP head ----------------
__global__ void head_kernel(const float* __restrict__ w1, const float* __restrict__ b1,
                            const float* __restrict__ w2, const float* __restrict__ b2,
                            float* __restrict__ out) {
    const int b = blockIdx.x;
    const int j = threadIdx.x;  // 64
    const float* last = g_xbuf + ((long)b * SEQ + (SEQ - 1)) * DMODEL;
    const float* wr = w1 + (long)j * DMODEL;
    float s = 0.f;
    for (int c = 0; c < DMODEL; c++) s += last[c] * __ldg(&wr[c]);
    s = fmaxf(s + __ldg(&b1[j]), 0.f);
    __shared__ float sh[64];
    sh[j] = s * __ldg(&w2[j]);
    __syncthreads();
    if (j == 0) {
        float tot = 0.f;
        for (int k = 0; k < 64; k++) tot += sh[k];
        out[b] = tot + __ldg(&b2[0]);
    }
}

// ---------------- launch ----------------
extern "C" void kernel_launch(void* const* d_in, const int* in_sizes, int n_in,
                              void* d_out, int out_size) {
    const float* x         = (const float*)d_in[0];
    const float* norm_w    = (const float*)d_in[1];
    const float* in_proj_w = (const float*)d_in[2];
    const float* conv_w    = (const float*)d_in[3];
    const float* conv_b    = (const float*)d_in[4];
    const float* x_proj_w  = (const float*)d_in[5];
    const float* dt_proj_w = (const float*)d_in[6];
    const float* dt_proj_b = (const float*)d_in[7];
    const float* A_log     = (const float*)d_in[8];
    const float* Dp        = (const float*)d_in[9];
    const float* out_proj_w= (const float*)d_in[10];
    const float* w1        = (const float*)d_in[11];
    const float* b1        = (const float*)d_in[12];
    const float* w2        = (const float*)d_in[13];
    const float* b2        = (const float*)d_in[14];

    float *p_xbuf, *p_xz, *p_dbc, *p_delta;
    cudaGetSymbolAddress((void**)&p_xbuf,  g_xbuf);
    cudaGetSymbolAddress((void**)&p_xz,    g_xz);
    cudaGetSymbolAddress((void**)&p_dbc,   g_dbc);
    cudaGetSymbolAddress((void**)&p_delta, g_delta);

    bf16 *p_xn_h, *p_xn_l, *p_xc_h, *p_xc_l, *p_y_h, *p_y_l, *p_dt_h, *p_dt_l;
    bf16 *p_inw_h, *p_inw_l, *p_outw_h, *p_outw_l, *p_xpw_h, *p_xpw_l, *p_dtw_h, *p_dtw_l;
    cudaGetSymbolAddress((void**)&p_xn_h, g_xn_h);   cudaGetSymbolAddress((void**)&p_xn_l, g_xn_l);
    cudaGetSymbolAddress((void**)&p_xc_h, g_xc_h);   cudaGetSymbolAddress((void**)&p_xc_l, g_xc_l);
    cudaGetSymbolAddress((void**)&p_y_h,  g_y_h);    cudaGetSymbolAddress((void**)&p_y_l,  g_y_l);
    cudaGetSymbolAddress((void**)&p_dt_h, g_dt_h);   cudaGetSymbolAddress((void**)&p_dt_l, g_dt_l);
    cudaGetSymbolAddress((void**)&p_inw_h, g_inw_h); cudaGetSymbolAddress((void**)&p_inw_l, g_inw_l);
    cudaGetSymbolAddress((void**)&p_outw_h, g_outw_h); cudaGetSymbolAddress((void**)&p_outw_l, g_outw_l);
    cudaGetSymbolAddress((void**)&p_xpw_h, g_xpw_h); cudaGetSymbolAddress((void**)&p_xpw_l, g_xpw_l);
    cudaGetSymbolAddress((void**)&p_dtw_h, g_dtw_h); cudaGetSymbolAddress((void**)&p_dtw_l, g_dtw_l);

    cudaFuncSetAttribute(hmma_gemm<0>, cudaFuncAttributeMaxDynamicSharedMemorySize, GSMEM);
    cudaFuncSetAttribute(hmma_gemm<1>, cudaFuncAttributeMaxDynamicSharedMemorySize, GSMEM);
    cudaFuncSetAttribute(hmma_gemm<2>, cudaFuncAttributeMaxDynamicSharedMemorySize, GSMEM);
    cudaFuncSetAttribute(hmma_gemm<3>, cudaFuncAttributeMaxDynamicSharedMemorySize, GSMEM);

    // residual stream = input x
    cudaMemcpyAsync(p_xbuf, x, sizeof(float) * (size_t)TOK * DMODEL,
                    cudaMemcpyDeviceToDevice, 0);

    // ---- weight conversion ----
    {
        const int n_in_w  = NLAYERS * 2*ED * DMODEL;
        const int n_out_w = NLAYERS * DMODEL * ED;
        const int n_xp_w  = NLAYERS * 64 * ED;
        const int n_dt_w  = NLAYERS * ED * DTRANK;
        cvt_split<<<(n_in_w  + 255)/256, 256>>>(in_proj_w,  p_inw_h,  p_inw_l,  n_in_w);
        cvt_split<<<(n_out_w + 255)/256, 256>>>(out_proj_w, p_outw_h, p_outw_l, n_out_w);
        cvt_split<<<(n_xp_w  + 255)/256, 256>>>(x_proj_w,   p_xpw_h,  p_xpw_l,  n_xp_w);
        cvt_split<<<(n_dt_w  + 255)/256, 256>>>(dt_proj_w,  p_dtw_h,  p_dtw_l,  n_dt_w);
    }

    for (int l = 0; l < NLAYERS; l++) {
        // 1) rmsnorm -> xn hi/lo
        rmsnorm_kernel<<<TOK, 128>>>(norm_w + (long)l * DMODEL);

        // 2) in_proj: [4096,512]x[2048,512]^T -> xz fp32
        hmma_gemm<0><<<dim3(2*ED/64, TOK/128), 256, GSMEM>>>(
            p_xn_h, p_xn_l, DMODEL,
            p_inw_h + (long)l * 2*ED * DMODEL, p_inw_l + (long)l * 2*ED * DMODEL,
            p_xz, 2*ED, DMODEL, nullptr);

        // 3) conv + silu -> xc fp32 + hi/lo
        conv_silu_kernel<<<TOK * ED / 256, 256>>>(conv_w + (long)l * ED * DCONV,
                                                  conv_b + (long)l * ED);

        // 4) x_proj: [4096,1024]x[64,1024]^T -> dbc fp32 + fused dt hi/lo split
        hmma_gemm<3><<<dim3(1, TOK/128), 256, GSMEM>>>(
            p_xc_h, p_xc_l, ED,
            p_xpw_h + (long)l * 64 * ED, p_xpw_l + (long)l * 64 * ED,
            p_dbc, 64, ED, nullptr);

        // 5) dt_proj + softplus: [4096,32]x[1024,32]^T -> delta
        hmma_gemm<1><<<dim3(ED/64, TOK/128), 256, GSMEM>>>(
            p_dt_h, p_dt_l, DTRANK,
            p_dtw_h + (long)l * ED * DTRANK, p_dtw_l + (long)l * ED * DTRANK,
            p_delta, ED, DTRANK, dt_proj_b + (long)l * ED);

        // 6) scan -> y hi/lo
        scan_kernel<<<(BATCH * ED * 4) / 256, 256>>>(A_log + (long)l * ED * DSTATE,
                                                     Dp + (long)l * ED);

        // 7) out_proj + residual: [4096,1024]x[512,1024]^T += xbuf
        hmma_gemm<2><<<dim3(DMODEL/64, TOK/128), 256, GSMEM>>>(
            p_y_h, p_y_l, ED,
            p_outw_h + (long)l * DMODEL * ED, p_outw_l + (long)l * DMODEL * ED,
            p_xbuf, DMODEL, ED, nullptr);
    }

    head_kernel<<<BATCH, 64>>>(w1, b1, w2, b2, (float*)d_out);
}